// round 16
// baseline (speedup 1.0000x reference)
#include <cuda_runtime.h>

#define FULL 0xffffffffu
typedef unsigned long long ull;

__device__ __forceinline__ ull f2pack2(float v) {
    ull r;
    unsigned u = __float_as_uint(v);
    asm("mov.b64 %0, {%1, %1};" : "=l"(r) : "r"(u));
    return r;
}
__device__ __forceinline__ void f2unpack(float& lo, float& hi, ull v) {
    unsigned l, h;
    asm("mov.b64 {%0, %1}, %2;" : "=r"(l), "=r"(h) : "l"(v));
    lo = __uint_as_float(l);
    hi = __uint_as_float(h);
}
__device__ __forceinline__ ull fma2(ull a, ull b, ull c) {
    ull d;
    asm("fma.rn.f32x2 %0, %1, %2, %3;" : "=l"(d) : "l"(a), "l"(b), "l"(c));
    return d;
}

// ---------------- scratch for neighbor indices (no allocation) --------------
#define MAXN 8192
__device__ unsigned g_nbr[MAXN * 32];

// ============================================================================
// Kernel A: top-32 nearest neighbors per agent (one warp per agent).
// ============================================================================
#define A_WARPS 16
#define A_TPB (A_WARPS * 32)

__global__ __launch_bounds__(A_TPB, 2) void topk_kernel(
    const float* __restrict__ states, int n)
{
    extern __shared__ float2 sxy[];
    const int tid  = threadIdx.x;
    const int lane = tid & 31;
    const int warp = tid >> 5;

    for (int j = tid; j < n; j += A_TPB) {
        const float4 s = ((const float4*)states)[j];
        sxy[j] = make_float2(s.x, s.y);
    }
    __syncthreads();

    const int i = blockIdx.x * A_WARPS + warp;
    if (i >= n) return;

    const float2 pi = sxy[i];
    const float six = pi.x, siy = pi.y;

    auto make_key = [&](int j) -> unsigned long long {
        const float2 p = sxy[j];
        const float dx = six - p.x;
        const float dy = siy - p.y;
        const float d2 = __fadd_rn(__fadd_rn(__fmul_rn(dx, dx), __fmul_rn(dy, dy)), 1e-4f);
        const float d  = __fsqrt_rn(d2);
        return ((unsigned long long)__float_as_uint(d) << 32) | (unsigned)j;
    };

    unsigned long long R = make_key(lane);
#pragma unroll
    for (int k = 2; k <= 32; k <<= 1) {
#pragma unroll
        for (int jj = k >> 1; jj > 0; jj >>= 1) {
            const unsigned long long other = __shfl_xor_sync(FULL, R, jj);
            const bool takeMin = (((lane & jj) == 0) == ((lane & k) == 0));
            const unsigned long long mn = (R < other) ? R : other;
            const unsigned long long mx = (R < other) ? other : R;
            R = takeMin ? mn : mx;
        }
    }
    unsigned long long keyMax = __shfl_sync(FULL, R, 31);

#pragma unroll 2
    for (int base = 32; base < n; base += 32) {
        const unsigned long long key = make_key(base + lane);
        unsigned cm = __ballot_sync(FULL, key < keyMax);
        if (cm) {
            do {
                const int c = __ffs(cm) - 1;
                cm &= cm - 1;
                const unsigned long long k = __shfl_sync(FULL, key, c);
                const int pos = __popc(__ballot_sync(FULL, R < k));
                const unsigned long long up = __shfl_up_sync(FULL, R, 1);
                R = (lane < pos) ? R : (lane == pos ? k : up);
            } while (cm);
            keyMax = __shfl_sync(FULL, R, 31);
        }
    }

    g_nbr[i * 32 + lane] = (unsigned)(R & 0xffffffffull);
}

// ============================================================================
// Kernel B: features + conv1 + block-GEMM conv2 (f32x2) + argmax + coop MLP.
// Only change vs R14: GEMM inner product uses packed position-pairs.
// ============================================================================
#define KWARPS 8
#define TPB (KWARPS * 32)
#define WSCR_FLOATS 272
#define UNION_FLOATS 25344

__global__ __launch_bounds__(TPB, 2) void conv_mlp_kernel(
    const float* __restrict__ states, const float* __restrict__ goals,
    const float* __restrict__ W1, const float* __restrict__ b1,
    const float* __restrict__ W2, const float* __restrict__ b2,
    const float* __restrict__ Wd1, const float* __restrict__ bd1,
    const float* __restrict__ Wd2, const float* __restrict__ bd2,
    const float* __restrict__ Wd3, const float* __restrict__ bd3,
    const float* __restrict__ Wd4, const float* __restrict__ bd4,
    float* __restrict__ out, int n)
{
    extern __shared__ float smem[];
    float* U     = smem;
    float* O1s   = U;                      // 16384 (phase 3)
    float* W2Ts  = U + 16384;              // 8448  (phase 3, stride 132)
    float* W1s   = U + 24832;              // 320
    float* b1s   = U + 25152;              // 64
    float* b2s   = U + 25216;              // 128
    float* Wd1s  = U;                      // 8448  (phase 4)
    float* Wd2s  = U + 8448;               // 8192
    float* Wd3s  = U + 16640;              // 8192
    float* Wd4s  = U + 24832;              // 256
    float* msks  = U + UNION_FLOATS;       // 256
    float* featS = msks + 256;             // 1056 (8 x 132)
    float* wscr0 = featS + 1056;           // 8 x 272

    const int tid  = threadIdx.x;
    const int lane = tid & 31;
    const int warp = tid >> 5;

    const float4* st4 = (const float4*)states;

    for (int idx = tid; idx < 8192; idx += TPB) {
        const int q = idx >> 6, c = idx & 63;
        W2Ts[c * 132 + q] = W2[idx];
    }
    for (int j = tid; j < 320; j += TPB) W1s[j] = W1[j];
    for (int j = tid; j < 64;  j += TPB) b1s[j] = b1[j];
    for (int j = tid; j < 128; j += TPB) b2s[j] = b2[j];
    __syncthreads();

    const int i = blockIdx.x * KWARPS + warp;
    const bool active = (i < n);

    float* wscr = wscr0 + warp * WSCR_FLOATS;
    float* xks  = wscr;          // 160 (dead after conv1)
    float* z1s  = wscr;          // 64  (aliases xks)
    float* z2s  = wscr + 64;     // 128
    float* z3s  = wscr + 192;    // 64
    float* kS   = wscr + 256;    // 4

    float4 si = make_float4(0.f, 0.f, 0.f, 0.f);

    if (active) {
        si = st4[i];

        const int j = (int)g_nbr[i * 32 + lane];
        const float4 sj = st4[j];
        const float x0 = si.x - sj.x;
        const float x1 = si.y - sj.y;
        const float x2 = si.z - sj.z;
        const float x3 = si.w - sj.w;
        const float x4 = (j == i) ? 1.0f : 0.0f;
        const float dist = __fsqrt_rn(__fadd_rn(__fmul_rn(x0, x0), __fmul_rn(x1, x1)));
        msks[32 * warp + lane] = (dist < 1.0f) ? 1.0f : 0.0f;

        xks[lane * 5 + 0] = x0;
        xks[lane * 5 + 1] = x1;
        xks[lane * 5 + 2] = x2;
        xks[lane * 5 + 3] = x3;
        xks[lane * 5 + 4] = x4;
        __syncwarp();

        const float h0 = xks[  0 + lane];
        const float h1 = xks[ 32 + lane];
        const float h2 = xks[ 64 + lane];
        const float h3 = xks[ 96 + lane];
        const float h4 = xks[128 + lane];

        // conv1 5 -> 64 (bitwise-exact chain), to shared
        const int col = 32 * warp + lane;
#pragma unroll 8
        for (int c = 0; c < 64; ++c) {
            const float* w = W1s + c * 5;
            float a = __fmul_rn(w[0], h0);
            a = fmaf(w[1], h1, a);
            a = fmaf(w[2], h2, a);
            a = fmaf(w[3], h3, a);
            a = fmaf(w[4], h4, a);
            a = __fadd_rn(a, b1s[c]);
            O1s[c * 256 + col] = fmaxf(a, 0.0f);
        }

        if (lane == 0) {
            const float2 g = ((const float2*)goals)[i];
            float* fA = featS + warp * 132;
            fA[128] = si.x - g.x;
            fA[129] = si.y - g.y;
            fA[130] = si.z;
            fA[131] = si.w;
        }
    }
    __syncthreads();

    // -------- block GEMM (128q x 256col, k=64) with f32x2 position-pairs ----
    // Each ull accumulator holds cols (2p, 2p+1); each half runs the exact
    // c = 0..63 fmaf chain (weight duplicated into both halves).
    {
        float mk[8];
        {
            const float4 m0 = *(const float4*)(msks + lane * 4);
            const float4 m1 = *(const float4*)(msks + 128 + lane * 4);
            mk[0] = m0.x; mk[1] = m0.y; mk[2] = m0.z; mk[3] = m0.w;
            mk[4] = m1.x; mk[5] = m1.y; mk[6] = m1.z; mk[7] = m1.w;
        }
        const int agentA = lane >> 3;            // 0..3
        const int psub   = (lane & 7) * 4;       // first position of this thread

        for (int pass = 0; pass < 2; ++pass) {
            const int qbase = pass * 64 + warp * 8;
            ull acc2[8][4];
#pragma unroll
            for (int a = 0; a < 8; ++a)
#pragma unroll
                for (int p = 0; p < 4; ++p) acc2[a][p] = 0ull;

            const float* wp = W2Ts + qbase;
#pragma unroll 2
            for (int c = 0; c < 64; ++c) {
                const float4 wv0 = *(const float4*)(wp + c * 132);
                const float4 wv1 = *(const float4*)(wp + c * 132 + 4);
                const ulonglong2 o0 = *(const ulonglong2*)(O1s + c * 256 + lane * 4);
                const ulonglong2 o1 = *(const ulonglong2*)(O1s + c * 256 + 128 + lane * 4);
                const ull op[4] = {o0.x, o0.y, o1.x, o1.y};
                const ull wd[8] = {
                    f2pack2(wv0.x), f2pack2(wv0.y), f2pack2(wv0.z), f2pack2(wv0.w),
                    f2pack2(wv1.x), f2pack2(wv1.y), f2pack2(wv1.z), f2pack2(wv1.w)};
#pragma unroll
                for (int a = 0; a < 8; ++a)
#pragma unroll
                    for (int p = 0; p < 4; ++p)
                        acc2[a][p] = fma2(wd[a], op[p], acc2[a][p]);
            }

#pragma unroll
            for (int a = 0; a < 8; ++a) {
                const int q = qbase + a;
                const float bq = b2s[q];
                float acc[8];
#pragma unroll
                for (int p = 0; p < 4; ++p)
                    f2unpack(acc[2 * p], acc[2 * p + 1], acc2[a][p]);

                // agent A over b=0..3, agent A+4 over b=4..7
                unsigned bestL = 0u; int bpL = psub;
                unsigned bestH = 0u; int bpH = psub;
#pragma unroll
                for (int b = 0; b < 4; ++b) {
                    const float v = __fmul_rn(
                        fmaxf(__fadd_rn(acc[b], bq), 0.0f), mk[b]);
                    const unsigned vb = __float_as_uint(v);
                    if (vb > bestL) { bestL = vb; bpL = psub + b; }
                }
#pragma unroll
                for (int b = 4; b < 8; ++b) {
                    const float v = __fmul_rn(
                        fmaxf(__fadd_rn(acc[b], bq), 0.0f), mk[b]);
                    const unsigned vb = __float_as_uint(v);
                    if (vb > bestH) { bestH = vb; bpH = psub + b - 4; }
                }
                unsigned long long keyL =
                    ((unsigned long long)bestL << 5) | (unsigned)(31 - bpL);
                unsigned long long keyH =
                    ((unsigned long long)bestH << 5) | (unsigned)(31 - bpH);
#pragma unroll
                for (int o = 1; o < 8; o <<= 1) {
                    const unsigned long long oL = __shfl_xor_sync(FULL, keyL, o);
                    const unsigned long long oH = __shfl_xor_sync(FULL, keyH, o);
                    keyL = (oL > keyL) ? oL : keyL;
                    keyH = (oH > keyH) ? oH : keyH;
                }
                if ((lane & 7) == 0) {
                    featS[agentA * 132 + q]       = (float)(31 - (int)(keyL & 31ull));
                    featS[(agentA + 4) * 132 + q] = (float)(31 - (int)(keyH & 31ull));
                }
            }
        }
    }
    __syncthreads();

    // -------- stage MLP weights into the dead union region (once/block) -----
    {
        const float4* s1 = (const float4*)Wd1;
        const float4* s2 = (const float4*)Wd2;
        const float4* s3 = (const float4*)Wd3;
        const float4* s4 = (const float4*)Wd4;
        float4* d1 = (float4*)Wd1s;
        float4* d2 = (float4*)Wd2s;
        float4* d3 = (float4*)Wd3s;
        float4* d4 = (float4*)Wd4s;
        for (int t = tid; t < 2112; t += TPB) d1[t] = s1[t];
        for (int t = tid; t < 2048; t += TPB) d2[t] = s2[t];
        for (int t = tid; t < 2048; t += TPB) d3[t] = s3[t];
        for (int t = tid; t < 64;   t += TPB) d4[t] = s4[t];
    }
    __syncthreads();

    // -------- cooperative MLP 132 -> 64 -> 128 -> 64 -> 4 (reassociated) ----
    if (!active) return;
    {
        const float* fA = featS + warp * 132;
        const float4 f4 = *(const float4*)(fA + lane * 4);
        const float  ft = (lane < 4) ? fA[128 + lane] : 0.0f;

        for (int nn = 0; nn < 64; nn += 2) {
#pragma unroll
            for (int s = 0; s < 2; ++s) {
                const int m = nn + s;
                const float4 w = *(const float4*)(Wd1s + m * 132 + lane * 4);
                float p = w.x * f4.x;
                p = fmaf(w.y, f4.y, p);
                p = fmaf(w.z, f4.z, p);
                p = fmaf(w.w, f4.w, p);
                if (lane < 4) p = fmaf(Wd1s[m * 132 + 128 + lane], ft, p);
#pragma unroll
                for (int o = 16; o; o >>= 1) p += __shfl_xor_sync(FULL, p, o);
                if (lane == 0) z1s[m] = fmaxf(p + bd1[m], 0.0f);
            }
        }
        __syncwarp();

        const float2 zv1 = *(const float2*)(z1s + lane * 2);
        for (int nn = 0; nn < 128; nn += 2) {
#pragma unroll
            for (int s = 0; s < 2; ++s) {
                const int m = nn + s;
                const float2 w = *(const float2*)(Wd2s + m * 64 + lane * 2);
                float p = fmaf(w.y, zv1.y, w.x * zv1.x);
#pragma unroll
                for (int o = 16; o; o >>= 1) p += __shfl_xor_sync(FULL, p, o);
                if (lane == 0) z2s[m] = fmaxf(p + bd2[m], 0.0f);
            }
        }
        __syncwarp();

        const float4 zv2 = *(const float4*)(z2s + lane * 4);
        for (int nn = 0; nn < 64; nn += 2) {
#pragma unroll
            for (int s = 0; s < 2; ++s) {
                const int m = nn + s;
                const float4 w = *(const float4*)(Wd3s + m * 128 + lane * 4);
                float p = w.x * zv2.x;
                p = fmaf(w.y, zv2.y, p);
                p = fmaf(w.z, zv2.z, p);
                p = fmaf(w.w, zv2.w, p);
#pragma unroll
                for (int o = 16; o; o >>= 1) p += __shfl_xor_sync(FULL, p, o);
                if (lane == 0) z3s[m] = fmaxf(p + bd3[m], 0.0f);
            }
        }
        __syncwarp();

        const float2 zv3 = *(const float2*)(z3s + lane * 2);
#pragma unroll
        for (int m = 0; m < 4; ++m) {
            const float2 w = *(const float2*)(Wd4s + m * 64 + lane * 2);
            float p = fmaf(w.y, zv3.y, w.x * zv3.x);
#pragma unroll
            for (int o = 16; o; o >>= 1) p += __shfl_xor_sync(FULL, p, o);
            if (lane == 0)
                kS[m] = 2.0f / (1.0f + expf(-(p + bd4[m]))) + 0.2f;
        }
        __syncwarp();

        if (lane == 0) {
            const float k0 = kS[0], k1 = kS[1], k2 = kS[2], k3 = kS[3];
            const float relx = fA[128], rely = fA[129];
            const float vx = si.z, vy = si.w;
            const float ax = -__fadd_rn(__fmul_rn(k0, relx), __fmul_rn(k1, vx));
            const float ay = -__fadd_rn(__fmul_rn(k2, rely), __fmul_rn(k3, vy));
            ((float2*)out)[i] = make_float2(ax, ay);
        }
    }
}

extern "C" void kernel_launch(void* const* d_in, const int* in_sizes, int n_in,
                              void* d_out, int out_size)
{
    const float* states = (const float*)d_in[0];
    const float* goals  = (const float*)d_in[1];
    const float* W1  = (const float*)d_in[2];
    const float* b1  = (const float*)d_in[3];
    const float* W2  = (const float*)d_in[4];
    const float* b2  = (const float*)d_in[5];
    const float* Wd1 = (const float*)d_in[6];
    const float* bd1 = (const float*)d_in[7];
    const float* Wd2 = (const float*)d_in[8];
    const float* bd2 = (const float*)d_in[9];
    const float* Wd3 = (const float*)d_in[10];
    const float* bd3 = (const float*)d_in[11];
    const float* Wd4 = (const float*)d_in[12];
    const float* bd4 = (const float*)d_in[13];

    const int n = in_sizes[0] / 4;

    {
        const int blocks = (n + A_WARPS - 1) / A_WARPS;
        const size_t smemA = (size_t)n * sizeof(float2);
        cudaFuncSetAttribute(topk_kernel,
                             cudaFuncAttributeMaxDynamicSharedMemorySize, (int)smemA);
        topk_kernel<<<blocks, A_TPB, smemA>>>(states, n);
    }
    {
        const int blocks = (n + KWARPS - 1) / KWARPS;
        const size_t smem_floats = UNION_FLOATS + 256 + 1056
                                 + (size_t)KWARPS * WSCR_FLOATS;
        const size_t smemB = smem_floats * sizeof(float);
        cudaFuncSetAttribute(conv_mlp_kernel,
                             cudaFuncAttributeMaxDynamicSharedMemorySize, (int)smemB);
        conv_mlp_kernel<<<blocks, TPB, smemB>>>(
            states, goals, W1, b1, W2, b2,
            Wd1, bd1, Wd2, bd2, Wd3, bd3, Wd4, bd4,
            (float*)d_out, n);
    }
}